// round 13
// baseline (speedup 1.0000x reference)
#include <cuda_runtime.h>

// Problem shapes (fixed by the reference)
#define MDIM 16384
#define NDIM 16384
#define BC   8           // B * C_IN = 2*4
#define CHUNK 256        // m-chunk per stage: 8 * 256 * 4B = 8 KB
#define NCHUNK (MDIM / CHUNK)          // 64
#define CH_BYTES (CHUNK * 4)           // 1 KB per channel per chunk
#define STAGE_BYTES (BC * CH_BYTES)    // 8 KB per chunk
#define ROWS_PER_BLOCK 16
#define THREADS 128      // 4 warps; each warp owns 4 rows

__device__ __forceinline__ unsigned smem_u32(const void* p) {
    unsigned a;
    asm("{ .reg .u64 t; cvta.to.shared.u64 t, %1; cvt.u32.u64 %0, t; }"
        : "=r"(a) : "l"(p));
    return a;
}

__device__ __forceinline__ void mbar_init(unsigned addr, unsigned count) {
    asm volatile("mbarrier.init.shared.b64 [%0], %1;" :: "r"(addr), "r"(count) : "memory");
}

__device__ __forceinline__ void mbar_expect_tx(unsigned addr, unsigned bytes) {
    asm volatile("mbarrier.arrive.expect_tx.shared.b64 _, [%0], %1;"
                 :: "r"(addr), "r"(bytes) : "memory");
}

__device__ __forceinline__ void mbar_wait(unsigned addr, unsigned parity) {
    unsigned done;
    asm volatile(
        "{\n\t.reg .pred p;\n\t"
        "mbarrier.try_wait.parity.acquire.cta.shared::cta.b64 p, [%1], %2;\n\t"
        "selp.b32 %0, 1, 0, p;\n\t}"
        : "=r"(done) : "r"(addr), "r"(parity) : "memory");
    if (!done) {
        asm volatile(
            "{\n\t.reg .pred P1;\n\t"
            "WL_%=:\n\t"
            "mbarrier.try_wait.parity.acquire.cta.shared::cta.b64 P1, [%0], %1, 0x989680;\n\t"
            "@P1 bra.uni WD_%=;\n\t"
            "bra.uni WL_%=;\n\t"
            "WD_%=:\n\t}"
            :: "r"(addr), "r"(parity) : "memory");
    }
}

__device__ __forceinline__ void tma_bulk_1d(unsigned smem_dst, const void* gsrc,
                                            unsigned bytes, unsigned mbar) {
    asm volatile(
        "cp.async.bulk.shared::cluster.global.mbarrier::complete_tx::bytes "
        "[%0], [%1], %2, [%3];"
        :: "r"(smem_dst), "l"(gsrc), "r"(bytes), "r"(mbar) : "memory");
}

// y[b,o,n] = sum_c theta[o,c] * (sum_m D[n,m] x[b,c,m]) + bias[o]
// Single-wave launch (1024 blocks, 7/SM). x chunks arrive via double-buffered
// TMA bulk copies so the SM's L1 pipeline only carries D LDGs and x LDSs.
__global__ __launch_bounds__(THREADS, 7)
void coboundary_kernel(const float* __restrict__ D,
                       const float* __restrict__ x,      // [8][MDIM]
                       const float* __restrict__ theta,  // [8][4]
                       const float* __restrict__ bias,   // [8]
                       float* __restrict__ out)          // [16][NDIM]
{
    __shared__ alignas(128) float sx[2][BC][CHUNK];
    __shared__ alignas(8) unsigned long long mbar_store[2];

    const int tid = threadIdx.x;
    const int tx  = tid & 31;        // lane
    const int ty  = tid >> 5;        // warp 0..3
    const int row0 = blockIdx.x * ROWS_PER_BLOCK + ty * 4;

    const unsigned mb0 = smem_u32(&mbar_store[0]);
    const unsigned mb1 = smem_u32(&mbar_store[1]);

    if (tid == 0) {
        mbar_init(mb0, 1);
        mbar_init(mb1, 1);
    }
    __syncthreads();

    // Prologue: prefetch chunks 0 and 1.
    if (tid == 0) {
#pragma unroll 1
        for (int c = 0; c < 2; ++c) {
            const unsigned mb = c ? mb1 : mb0;
            mbar_expect_tx(mb, STAGE_BYTES);
#pragma unroll
            for (int bc = 0; bc < BC; ++bc)
                tma_bulk_1d(smem_u32(&sx[c][bc][0]),
                            x + (size_t)bc * MDIM + c * CHUNK,
                            CH_BYTES, mb);
        }
    }

    float acc[4][BC];
#pragma unroll
    for (int r = 0; r < 4; ++r)
#pragma unroll
        for (int c = 0; c < BC; ++c) acc[r][c] = 0.0f;

    const float* __restrict__ Drow = D + (size_t)row0 * MDIM;

    for (int c = 0; c < NCHUNK; ++c) {
        const int buf = c & 1;
        const unsigned mb = buf ? mb1 : mb0;
        mbar_wait(mb, (c >> 1) & 1);

#pragma unroll
        for (int i = 0; i < CHUNK / 128; ++i) {
            const int mo = i * 128 + tx * 4;
            const float* dbase = Drow + c * CHUNK + mo;

            // Batch the 4 row loads (MLP=4/thread, coalesced, streaming).
            float4 d[4];
#pragma unroll
            for (int r = 0; r < 4; ++r)
                d[r] = __ldcs(reinterpret_cast<const float4*>(
                    dbase + (size_t)r * MDIM));

#pragma unroll
            for (int bc = 0; bc < BC; ++bc) {
                const float4 xs =
                    *reinterpret_cast<const float4*>(&sx[buf][bc][mo]);
#pragma unroll
                for (int r = 0; r < 4; ++r) {
                    acc[r][bc] = fmaf(d[r].x, xs.x, acc[r][bc]);
                    acc[r][bc] = fmaf(d[r].y, xs.y, acc[r][bc]);
                    acc[r][bc] = fmaf(d[r].z, xs.z, acc[r][bc]);
                    acc[r][bc] = fmaf(d[r].w, xs.w, acc[r][bc]);
                }
            }
        }

        // All reads of this buffer done -> safe to overwrite with chunk c+2.
        __syncthreads();
        if (tid == 0 && c + 2 < NCHUNK) {
            mbar_expect_tx(mb, STAGE_BYTES);
#pragma unroll
            for (int bc = 0; bc < BC; ++bc)
                tma_bulk_1d(smem_u32(&sx[buf][bc][0]),
                            x + (size_t)bc * MDIM + (c + 2) * CHUNK,
                            CH_BYTES, mb);
        }
    }

    // Butterfly reduction: every lane ends with the full row sums.
#pragma unroll
    for (int r = 0; r < 4; ++r)
#pragma unroll
        for (int c = 0; c < BC; ++c)
#pragma unroll
            for (int off = 16; off > 0; off >>= 1)
                acc[r][c] += __shfl_xor_sync(0xffffffffu, acc[r][c], off);

    // Epilogue: fold theta + bias. Warp owns 4 rows * 16 (b,o) = 64 outputs;
    // each lane writes 2.
    const int r = tx >> 3;        // 0..3
    const int k = tx & 7;         // 0..7
    const int n = row0 + r;
#pragma unroll
    for (int t = 0; t < 2; ++t) {
        const int bo = k + t * 8;     // 0..15
        const int b  = bo >> 3;
        const int o  = bo & 7;
        const float4 th = *reinterpret_cast<const float4*>(&theta[o * 4]);
        float y = bias[o];
        y = fmaf(th.x, acc[r][b * 4 + 0], y);
        y = fmaf(th.y, acc[r][b * 4 + 1], y);
        y = fmaf(th.z, acc[r][b * 4 + 2], y);
        y = fmaf(th.w, acc[r][b * 4 + 3], y);
        out[(size_t)bo * NDIM + n] = y;
    }
}

extern "C" void kernel_launch(void* const* d_in, const int* in_sizes, int n_in,
                              void* d_out, int out_size)
{
    const float* D     = (const float*)d_in[0];   // [16384,16384]
    const float* x     = (const float*)d_in[1];   // [2,4,16384]
    const float* theta = (const float*)d_in[2];   // [8,4]
    const float* bias  = (const float*)d_in[3];   // [1,8,1] -> 8 floats
    float* out = (float*)d_out;                   // [2,8,16384]

    const int blocks = NDIM / ROWS_PER_BLOCK;     // 1024 = single wave @ 7/SM
    coboundary_kernel<<<blocks, THREADS>>>(D, x, theta, bias, out);
}

// round 14
// speedup vs baseline: 1.0013x; 1.0013x over previous
#include <cuda_runtime.h>

// Problem shapes (fixed by the reference)
#define MDIM 16384
#define NDIM 16384
#define BC   8           // B * C_IN = 2*4
#define CHUNK 256        // m-chunk per stage: 8 * 256 * 4B = 8 KB
#define NCHUNK (MDIM / CHUNK)          // 64
#define CH_BYTES (CHUNK * 4)           // 1 KB per channel per chunk
#define STAGE_BYTES (BC * CH_BYTES)    // 8 KB per chunk
#define ROWS_PER_BLOCK 16
#define THREADS 128      // 4 warps; each warp owns 4 rows

__device__ __forceinline__ unsigned smem_u32(const void* p) {
    unsigned a;
    asm("{ .reg .u64 t; cvta.to.shared.u64 t, %1; cvt.u32.u64 %0, t; }"
        : "=r"(a) : "l"(p));
    return a;
}

__device__ __forceinline__ void mbar_init(unsigned addr, unsigned count) {
    asm volatile("mbarrier.init.shared.b64 [%0], %1;" :: "r"(addr), "r"(count) : "memory");
}

__device__ __forceinline__ void mbar_expect_tx(unsigned addr, unsigned bytes) {
    asm volatile("mbarrier.arrive.expect_tx.shared.b64 _, [%0], %1;"
                 :: "r"(addr), "r"(bytes) : "memory");
}

__device__ __forceinline__ void mbar_wait(unsigned addr, unsigned parity) {
    unsigned done;
    asm volatile(
        "{\n\t.reg .pred p;\n\t"
        "mbarrier.try_wait.parity.acquire.cta.shared::cta.b64 p, [%1], %2;\n\t"
        "selp.b32 %0, 1, 0, p;\n\t}"
        : "=r"(done) : "r"(addr), "r"(parity) : "memory");
    if (!done) {
        asm volatile(
            "{\n\t.reg .pred P1;\n\t"
            "WL_%=:\n\t"
            "mbarrier.try_wait.parity.acquire.cta.shared::cta.b64 P1, [%0], %1, 0x989680;\n\t"
            "@P1 bra.uni WD_%=;\n\t"
            "bra.uni WL_%=;\n\t"
            "WD_%=:\n\t}"
            :: "r"(addr), "r"(parity) : "memory");
    }
}

__device__ __forceinline__ void tma_bulk_1d(unsigned smem_dst, const void* gsrc,
                                            unsigned bytes, unsigned mbar) {
    asm volatile(
        "cp.async.bulk.shared::cluster.global.mbarrier::complete_tx::bytes "
        "[%0], [%1], %2, [%3];"
        :: "r"(smem_dst), "l"(gsrc), "r"(bytes), "r"(mbar) : "memory");
}

// y[b,o,n] = sum_c theta[o,c] * (sum_m D[n,m] x[b,c,m]) + bias[o]
// Single-wave launch (1024 blocks, 7/SM). x chunks arrive via double-buffered
// TMA bulk copies so the SM's L1 pipeline only carries D LDGs and x LDSs.
__global__ __launch_bounds__(THREADS, 7)
void coboundary_kernel(const float* __restrict__ D,
                       const float* __restrict__ x,      // [8][MDIM]
                       const float* __restrict__ theta,  // [8][4]
                       const float* __restrict__ bias,   // [8]
                       float* __restrict__ out)          // [16][NDIM]
{
    __shared__ alignas(128) float sx[2][BC][CHUNK];
    __shared__ alignas(8) unsigned long long mbar_store[2];

    const int tid = threadIdx.x;
    const int tx  = tid & 31;        // lane
    const int ty  = tid >> 5;        // warp 0..3
    const int row0 = blockIdx.x * ROWS_PER_BLOCK + ty * 4;

    const unsigned mb0 = smem_u32(&mbar_store[0]);
    const unsigned mb1 = smem_u32(&mbar_store[1]);

    if (tid == 0) {
        mbar_init(mb0, 1);
        mbar_init(mb1, 1);
    }
    __syncthreads();

    // Prologue: prefetch chunks 0 and 1.
    if (tid == 0) {
#pragma unroll 1
        for (int c = 0; c < 2; ++c) {
            const unsigned mb = c ? mb1 : mb0;
            mbar_expect_tx(mb, STAGE_BYTES);
#pragma unroll
            for (int bc = 0; bc < BC; ++bc)
                tma_bulk_1d(smem_u32(&sx[c][bc][0]),
                            x + (size_t)bc * MDIM + c * CHUNK,
                            CH_BYTES, mb);
        }
    }

    float acc[4][BC];
#pragma unroll
    for (int r = 0; r < 4; ++r)
#pragma unroll
        for (int c = 0; c < BC; ++c) acc[r][c] = 0.0f;

    const float* __restrict__ Drow = D + (size_t)row0 * MDIM;

    for (int c = 0; c < NCHUNK; ++c) {
        const int buf = c & 1;
        const unsigned mb = buf ? mb1 : mb0;
        mbar_wait(mb, (c >> 1) & 1);

#pragma unroll
        for (int i = 0; i < CHUNK / 128; ++i) {
            const int mo = i * 128 + tx * 4;
            const float* dbase = Drow + c * CHUNK + mo;

            // Batch the 4 row loads (MLP=4/thread, coalesced, streaming).
            float4 d[4];
#pragma unroll
            for (int r = 0; r < 4; ++r)
                d[r] = __ldcs(reinterpret_cast<const float4*>(
                    dbase + (size_t)r * MDIM));

#pragma unroll
            for (int bc = 0; bc < BC; ++bc) {
                const float4 xs =
                    *reinterpret_cast<const float4*>(&sx[buf][bc][mo]);
#pragma unroll
                for (int r = 0; r < 4; ++r) {
                    acc[r][bc] = fmaf(d[r].x, xs.x, acc[r][bc]);
                    acc[r][bc] = fmaf(d[r].y, xs.y, acc[r][bc]);
                    acc[r][bc] = fmaf(d[r].z, xs.z, acc[r][bc]);
                    acc[r][bc] = fmaf(d[r].w, xs.w, acc[r][bc]);
                }
            }
        }

        // All reads of this buffer done -> safe to overwrite with chunk c+2.
        __syncthreads();
        if (tid == 0 && c + 2 < NCHUNK) {
            mbar_expect_tx(mb, STAGE_BYTES);
#pragma unroll
            for (int bc = 0; bc < BC; ++bc)
                tma_bulk_1d(smem_u32(&sx[buf][bc][0]),
                            x + (size_t)bc * MDIM + (c + 2) * CHUNK,
                            CH_BYTES, mb);
        }
    }

    // Butterfly reduction: every lane ends with the full row sums.
#pragma unroll
    for (int r = 0; r < 4; ++r)
#pragma unroll
        for (int c = 0; c < BC; ++c)
#pragma unroll
            for (int off = 16; off > 0; off >>= 1)
                acc[r][c] += __shfl_xor_sync(0xffffffffu, acc[r][c], off);

    // Epilogue: fold theta + bias. Warp owns 4 rows * 16 (b,o) = 64 outputs;
    // each lane writes 2.
    const int r = tx >> 3;        // 0..3
    const int k = tx & 7;         // 0..7
    const int n = row0 + r;
#pragma unroll
    for (int t = 0; t < 2; ++t) {
        const int bo = k + t * 8;     // 0..15
        const int b  = bo >> 3;
        const int o  = bo & 7;
        const float4 th = *reinterpret_cast<const float4*>(&theta[o * 4]);
        float y = bias[o];
        y = fmaf(th.x, acc[r][b * 4 + 0], y);
        y = fmaf(th.y, acc[r][b * 4 + 1], y);
        y = fmaf(th.z, acc[r][b * 4 + 2], y);
        y = fmaf(th.w, acc[r][b * 4 + 3], y);
        out[(size_t)bo * NDIM + n] = y;
    }
}

extern "C" void kernel_launch(void* const* d_in, const int* in_sizes, int n_in,
                              void* d_out, int out_size)
{
    const float* D     = (const float*)d_in[0];   // [16384,16384]
    const float* x     = (const float*)d_in[1];   // [2,4,16384]
    const float* theta = (const float*)d_in[2];   // [8,4]
    const float* bias  = (const float*)d_in[3];   // [1,8,1] -> 8 floats
    float* out = (float*)d_out;                   // [2,8,16384]

    const int blocks = NDIM / ROWS_PER_BLOCK;     // 1024 = single wave @ 7/SM
    coboundary_kernel<<<blocks, THREADS>>>(D, x, theta, bias, out);
}

// round 15
// speedup vs baseline: 1.0217x; 1.0204x over previous
#include <cuda_runtime.h>

// Problem shapes (fixed by the reference)
#define MDIM 16384
#define NDIM 16384
#define BC   8           // B * C_IN = 2*4
#define CHUNK 256        // m-chunk per stage buffer: 8 * 256 * 4B = 8 KB
#define NCHUNK (MDIM / CHUNK)          // 64
#define ROWS_PER_BLOCK 16
#define THREADS 128      // 4 warps; each warp owns 4 rows

// cp.async helpers (16B, cache-global)
__device__ __forceinline__ unsigned smem_u32(const void* p) {
    unsigned a;
    asm("{ .reg .u64 t; cvta.to.shared.u64 t, %1; cvt.u32.u64 %0, t; }"
        : "=r"(a) : "l"(p));
    return a;
}
__device__ __forceinline__ void cp_async16(unsigned dst, const void* src) {
    asm volatile("cp.async.cg.shared.global [%0], [%1], 16;"
                 :: "r"(dst), "l"(src) : "memory");
}
__device__ __forceinline__ void cp_commit() {
    asm volatile("cp.async.commit_group;" ::: "memory");
}
template <int N>
__device__ __forceinline__ void cp_wait() {
    asm volatile("cp.async.wait_group %0;" :: "n"(N) : "memory");
}

// y[b,o,n] = sum_c theta[o,c] * (sum_m D[n,m] x[b,c,m]) + bias[o]
// Single-wave launch (1024 blocks, 7/SM). x chunks stream L2->SMEM via
// double-buffered cp.async so staging latency never sits on the critical path.
__global__ __launch_bounds__(THREADS, 7)
void coboundary_kernel(const float* __restrict__ D,
                       const float* __restrict__ x,      // [8][MDIM]
                       const float* __restrict__ theta,  // [8][4]
                       const float* __restrict__ bias,   // [8]
                       float* __restrict__ out)          // [16][NDIM]
{
    __shared__ alignas(128) float sx[2][BC][CHUNK];

    const int tid = threadIdx.x;
    const int tx  = tid & 31;        // lane
    const int ty  = tid >> 5;        // warp 0..3
    const int row0 = blockIdx.x * ROWS_PER_BLOCK + ty * 4;

    // Staging map: per chunk, 512 float4 = 8ch * 64 float4. Flat index
    // f = tid + k*128 (k=0..3): ch = f>>6, off4 = f&63. Coalesced LDG per ch.
    const int s_ch[4]  = { tid >> 6, (tid + 128) >> 6, (tid + 256) >> 6, (tid + 384) >> 6 };
    const int s_off[4] = { (tid & 63) * 4, (tid & 63) * 4, (tid & 63) * 4, (tid & 63) * 4 };

    // Prologue: prefetch chunks 0 and 1.
#pragma unroll
    for (int c = 0; c < 2; ++c) {
#pragma unroll
        for (int k = 0; k < 4; ++k)
            cp_async16(smem_u32(&sx[c][s_ch[k]][s_off[k]]),
                       x + (size_t)s_ch[k] * MDIM + c * CHUNK + s_off[k]);
        cp_commit();
    }

    float acc[4][BC];
#pragma unroll
    for (int r = 0; r < 4; ++r)
#pragma unroll
        for (int c = 0; c < BC; ++c) acc[r][c] = 0.0f;

    const float* __restrict__ Drow = D + (size_t)row0 * MDIM;

    for (int c = 0; c < NCHUNK; ++c) {
        const int buf = c & 1;

        cp_wait<1>();      // chunk c's copies (own thread) complete
        __syncthreads();   // all threads' copies visible to everyone

#pragma unroll
        for (int i = 0; i < CHUNK / 128; ++i) {
            const int mo = i * 128 + tx * 4;
            const float* dbase = Drow + c * CHUNK + mo;

            // Batch the 4 row loads (MLP=4/thread, coalesced, streaming).
            float4 d[4];
#pragma unroll
            for (int r = 0; r < 4; ++r)
                d[r] = __ldcs(reinterpret_cast<const float4*>(
                    dbase + (size_t)r * MDIM));

            // Interleave channels so only one xs float4 is live at a time.
#pragma unroll
            for (int bc = 0; bc < BC; ++bc) {
                const float4 xs =
                    *reinterpret_cast<const float4*>(&sx[buf][bc][mo]);
#pragma unroll
                for (int r = 0; r < 4; ++r) {
                    acc[r][bc] = fmaf(d[r].x, xs.x, acc[r][bc]);
                    acc[r][bc] = fmaf(d[r].y, xs.y, acc[r][bc]);
                    acc[r][bc] = fmaf(d[r].z, xs.z, acc[r][bc]);
                    acc[r][bc] = fmaf(d[r].w, xs.w, acc[r][bc]);
                }
            }
        }

        __syncthreads();   // everyone finished reading buf -> safe to refill
        if (c + 2 < NCHUNK) {
#pragma unroll
            for (int k = 0; k < 4; ++k)
                cp_async16(smem_u32(&sx[buf][s_ch[k]][s_off[k]]),
                           x + (size_t)s_ch[k] * MDIM + (c + 2) * CHUNK + s_off[k]);
        }
        cp_commit();       // commit even if empty: keeps wait_group<1> counting
    }

    // Butterfly reduction: every lane ends with the full row sums.
#pragma unroll
    for (int r = 0; r < 4; ++r)
#pragma unroll
        for (int c = 0; c < BC; ++c)
#pragma unroll
            for (int off = 16; off > 0; off >>= 1)
                acc[r][c] += __shfl_xor_sync(0xffffffffu, acc[r][c], off);

    // Epilogue: fold theta + bias. Warp owns 4 rows * 16 (b,o) = 64 outputs;
    // each lane writes 2.
    const int r = tx >> 3;        // 0..3
    const int k = tx & 7;         // 0..7
    const int n = row0 + r;
#pragma unroll
    for (int t = 0; t < 2; ++t) {
        const int bo = k + t * 8;     // 0..15
        const int b  = bo >> 3;
        const int o  = bo & 7;
        const float4 th = *reinterpret_cast<const float4*>(&theta[o * 4]);
        float y = bias[o];
        y = fmaf(th.x, acc[r][b * 4 + 0], y);
        y = fmaf(th.y, acc[r][b * 4 + 1], y);
        y = fmaf(th.z, acc[r][b * 4 + 2], y);
        y = fmaf(th.w, acc[r][b * 4 + 3], y);
        out[(size_t)bo * NDIM + n] = y;
    }
}

extern "C" void kernel_launch(void* const* d_in, const int* in_sizes, int n_in,
                              void* d_out, int out_size)
{
    const float* D     = (const float*)d_in[0];   // [16384,16384]
    const float* x     = (const float*)d_in[1];   // [2,4,16384]
    const float* theta = (const float*)d_in[2];   // [8,4]
    const float* bias  = (const float*)d_in[3];   // [1,8,1] -> 8 floats
    float* out = (float*)d_out;                   // [2,8,16384]

    const int blocks = NDIM / ROWS_PER_BLOCK;     // 1024 = single wave @ 7/SM
    coboundary_kernel<<<blocks, THREADS>>>(D, x, theta, bias, out);
}